// round 3
// baseline (speedup 1.0000x reference)
#include <cuda_runtime.h>
#include <math.h>

// Problem dims
#define NL  2
#define NB  2
#define T_  2048
#define C_  512
#define H_  8
#define FF_ 1024
#define HS_ 64
#define EPS_ 1.1920929e-07f

#define BT_  (NB * T_)        // 4096 rows
#define BTC_ (NB * T_ * C_)   // 2097152
#define BH_  (NB * H_)        // 16

// ---------------- scratch (device globals; no allocation allowed) ----------------
__device__ float g_xnorm[BTC_];
__device__ float g_hnorm[BTC_];
__device__ float g_q[BTC_];
__device__ float g_k[BTC_];
__device__ float g_v[BTC_];
__device__ float g_attn[BTC_];
__device__ float g_ff[NB * T_ * FF_];
__device__ float g_scores[(size_t)BH_ * T_ * T_];   // 256 MB

// ---------------- helpers ----------------
__global__ void copy_k(float* __restrict__ dst, const float* __restrict__ src, int n) {
    int i = blockIdx.x * blockDim.x + threadIdx.x;
    if (i < n) dst[i] = src[i];
}

// One block per row; C_=512 -> exactly 2 elements per thread at 256 threads.
__global__ __launch_bounds__(256) void rmsnorm_k(
    const float* __restrict__ x, const float* __restrict__ g, float* __restrict__ out)
{
    long row = blockIdx.x;
    const float* xr = x + row * C_;
    float* orow = out + row * C_;
    int tid = threadIdx.x;
    float v0 = xr[tid];
    float v1 = xr[tid + 256];
    float ss = v0 * v0 + v1 * v1;

    __shared__ float red[8];
    #pragma unroll
    for (int o = 16; o; o >>= 1) ss += __shfl_xor_sync(0xffffffffu, ss, o);
    if ((tid & 31) == 0) red[tid >> 5] = ss;
    __syncthreads();
    if (tid == 0) {
        float s = 0.f;
        #pragma unroll
        for (int w = 0; w < 8; w++) s += red[w];
        red[0] = rsqrtf(s * (1.0f / C_) + EPS_);
    }
    __syncthreads();
    float r = red[0];
    orow[tid]       = v0 * r * g[tid];
    orow[tid + 256] = v1 * r * g[tid + 256];
}

// Row softmax over T_ columns; causal: valid length = t+1, tail zeroed.
__global__ __launch_bounds__(256) void softmax_k(float* __restrict__ S, int causal)
{
    long bh = blockIdx.y;
    int t = blockIdx.x;
    float* row = S + (bh * T_ + (long)t) * T_;
    int len = causal ? (t + 1) : T_;
    int tid = threadIdx.x;
    __shared__ float red[8];

    float m = -INFINITY;
    for (int i = tid; i < len; i += 256) m = fmaxf(m, row[i]);
    #pragma unroll
    for (int o = 16; o; o >>= 1) m = fmaxf(m, __shfl_xor_sync(0xffffffffu, m, o));
    if ((tid & 31) == 0) red[tid >> 5] = m;
    __syncthreads();
    if (tid == 0) {
        float mm = red[0];
        #pragma unroll
        for (int w = 1; w < 8; w++) mm = fmaxf(mm, red[w]);
        red[0] = mm;
    }
    __syncthreads();
    m = red[0];
    __syncthreads();

    float s = 0.f;
    for (int i = tid; i < len; i += 256) {
        float e = __expf(row[i] - m);
        row[i] = e;
        s += e;
    }
    #pragma unroll
    for (int o = 16; o; o >>= 1) s += __shfl_xor_sync(0xffffffffu, s, o);
    if ((tid & 31) == 0) red[tid >> 5] = s;
    __syncthreads();
    if (tid == 0) {
        float ss = 0.f;
        #pragma unroll
        for (int w = 0; w < 8; w++) ss += red[w];
        red[0] = ss;
    }
    __syncthreads();
    float inv = 1.0f / red[0];
    for (int i = tid; i < len; i += 256) row[i] *= inv;
    for (int i = tid; i < T_; i += 256) if (i >= len) row[i] = 0.f;
}

// ---------------- generic tiled GEMM ----------------
// C[m,n] (+)= act( alpha * sum_k A[m,k]*B[k,n] + bias[n] )
// B indexed as B[k*ldbk + n*ldbn] (covers normal and transposed layouts).
// Per-z offsets: z -> (b = z/Hdiv, h = z%Hdiv); pointer += b*Xb + h*Xh.
// Tile 64x64, BK=16, 256 threads, 4x4 per-thread microtile.
// All dims here are multiples of 64/16 so no bounds checks.
__global__ __launch_bounds__(256) void gemm_k(
    int M, int N, int K, float alpha,
    const float* __restrict__ A, int lda, long Ab, long Ah,
    const float* __restrict__ B, int ldbk, int ldbn, long Bb, long Bh,
    const float* __restrict__ bias,
    float* __restrict__ Cp, int ldc, long Cb, long Ch,
    int Hdiv, int accumulate, int gelu_act)
{
    int z = blockIdx.z;
    int b = z / Hdiv, h = z % Hdiv;
    A  += b * Ab + h * Ah;
    B  += b * Bb + h * Bh;
    Cp += b * Cb + h * Ch;

    __shared__ float As[16][64];
    __shared__ float Bs[16][64];

    int tid = threadIdx.x;
    int tx = tid & 15, ty = tid >> 4;
    int row0 = blockIdx.y * 64, col0 = blockIdx.x * 64;

    float acc[4][4] = {};

    int a_row = tid & 63;
    int a_k0  = (tid >> 6) * 4;
    int b_k   = tid >> 4;
    int b_n0  = (tid & 15) * 4;

    for (int k0 = 0; k0 < K; k0 += 16) {
        float4 av = *reinterpret_cast<const float4*>(
            &A[(long)(row0 + a_row) * lda + k0 + a_k0]);
        As[a_k0 + 0][a_row] = av.x;
        As[a_k0 + 1][a_row] = av.y;
        As[a_k0 + 2][a_row] = av.z;
        As[a_k0 + 3][a_row] = av.w;

        float4 bv;
        if (ldbn == 1) {
            bv = *reinterpret_cast<const float4*>(
                &B[(long)(k0 + b_k) * ldbk + col0 + b_n0]);
        } else {
            const float* bp = &B[(long)(k0 + b_k) * ldbk + (long)(col0 + b_n0) * ldbn];
            bv.x = bp[0];
            bv.y = bp[ldbn];
            bv.z = bp[2 * ldbn];
            bv.w = bp[3 * ldbn];
        }
        *reinterpret_cast<float4*>(&Bs[b_k][b_n0]) = bv;
        __syncthreads();

        #pragma unroll
        for (int kk = 0; kk < 16; kk++) {
            float4 a4 = *reinterpret_cast<const float4*>(&As[kk][ty * 4]);
            float4 b4 = *reinterpret_cast<const float4*>(&Bs[kk][tx * 4]);
            float ar[4] = {a4.x, a4.y, a4.z, a4.w};
            float br[4] = {b4.x, b4.y, b4.z, b4.w};
            #pragma unroll
            for (int i = 0; i < 4; i++)
                #pragma unroll
                for (int j = 0; j < 4; j++)
                    acc[i][j] += ar[i] * br[j];
        }
        __syncthreads();
    }

    #pragma unroll
    for (int i = 0; i < 4; i++) {
        int r = row0 + ty * 4 + i;
        float* crow = &Cp[(long)r * ldc + col0 + tx * 4];
        #pragma unroll
        for (int j = 0; j < 4; j++) {
            float v = alpha * acc[i][j];
            if (bias) v += bias[col0 + tx * 4 + j];
            if (gelu_act) v = 0.5f * v * (1.0f + erff(v * 0.70710678118654752f));
            if (accumulate) crow[j] += v;
            else            crow[j]  = v;
        }
    }
}

// ---------------- orchestration ----------------
extern "C" void kernel_launch(void* const* d_in, const int* in_sizes, int n_in,
                              void* d_out, int out_size)
{
    const float* hidden = (const float*)d_in[0];
    const float* target = (const float*)d_in[1];
    const float* Wq_s = (const float*)d_in[2];
    const float* Wk_s = (const float*)d_in[3];
    const float* Wv_s = (const float*)d_in[4];
    const float* Wo_s = (const float*)d_in[5];
    const float* bo_s = (const float*)d_in[6];
    const float* Wq_x = (const float*)d_in[7];
    const float* Wk_x = (const float*)d_in[8];
    const float* Wv_x = (const float*)d_in[9];
    const float* Wo_x = (const float*)d_in[10];
    const float* bo_x = (const float*)d_in[11];
    const float* W1 = (const float*)d_in[12];
    const float* b1 = (const float*)d_in[13];
    const float* W2 = (const float*)d_in[14];
    const float* b2 = (const float*)d_in[15];
    const float* g1 = (const float*)d_in[16];
    const float* g2 = (const float*)d_in[17];
    const float* g3 = (const float*)d_in[18];
    const float* g4 = (const float*)d_in[19];

    float* t = (float*)d_out;

    float *xnorm, *hnorm, *q, *k, *v, *attn, *ff, *scores;
    cudaGetSymbolAddress((void**)&xnorm, g_xnorm);
    cudaGetSymbolAddress((void**)&hnorm, g_hnorm);
    cudaGetSymbolAddress((void**)&q, g_q);
    cudaGetSymbolAddress((void**)&k, g_k);
    cudaGetSymbolAddress((void**)&v, g_v);
    cudaGetSymbolAddress((void**)&attn, g_attn);
    cudaGetSymbolAddress((void**)&ff, g_ff);
    cudaGetSymbolAddress((void**)&scores, g_scores);

    // t = target
    copy_k<<<(BTC_ + 255) / 256, 256>>>(t, target, BTC_);

    const long HCHS = (long)H_ * C_ * HS_;
    const long CHS  = (long)C_ * HS_;
    const long THS  = (long)T_ * HS_;
    const long TT   = (long)T_ * T_;

    dim3 gProj(1, T_ / 64, BH_);
    dim3 gQK(T_ / 64, T_ / 64, BH_);
    dim3 gPV(1, T_ / 64, BH_);
    dim3 gO(C_ / 64, BT_ / 64, 1);
    dim3 gF1(FF_ / 64, BT_ / 64, 1);
    dim3 gF2(C_ / 64, BT_ / 64, 1);
    dim3 gSm(T_, BH_);

    for (int l = 0; l < NL; l++) {
        // ======== masked self-attention ========
        rmsnorm_k<<<BT_, 256>>>(t, g1 + (long)l * C_, xnorm);

        // Q/K/V head projections: per (b,h): [T,C] x [C,HS]
        gemm_k<<<gProj, 256>>>(T_, HS_, C_, 1.f,
            xnorm, C_, (long)T_ * C_, 0,
            Wq_s + l * HCHS, HS_, 1, 0, CHS,
            nullptr,
            q, HS_, (long)H_ * THS, THS,
            H_, 0, 0);
        gemm_k<<<gProj, 256>>>(T_, HS_, C_, 1.f,
            xnorm, C_, (long)T_ * C_, 0,
            Wk_s + l * HCHS, HS_, 1, 0, CHS,
            nullptr,
            k, HS_, (long)H_ * THS, THS,
            H_, 0, 0);
        gemm_k<<<gProj, 256>>>(T_, HS_, C_, 1.f,
            xnorm, C_, (long)T_ * C_, 0,
            Wv_s + l * HCHS, HS_, 1, 0, CHS,
            nullptr,
            v, HS_, (long)H_ * THS, THS,
            H_, 0, 0);

        // S = (Q K^T) * HS^-0.5
        gemm_k<<<gQK, 256>>>(T_, T_, HS_, 0.125f,
            q, HS_, (long)H_ * THS, THS,
            k, 1, HS_, (long)H_ * THS, THS,
            nullptr,
            scores, T_, (long)H_ * TT, TT,
            H_, 0, 0);
        softmax_k<<<gSm, 256>>>(scores, 1);

        // attn[b,t,h*HS+d] = P V
        gemm_k<<<gPV, 256>>>(T_, HS_, T_, 1.f,
            scores, T_, (long)H_ * TT, TT,
            v, HS_, 1, (long)H_ * THS, THS,
            nullptr,
            attn, C_, (long)T_ * C_, HS_,
            H_, 0, 0);

        // t += attn @ Wo + bo
        gemm_k<<<gO, 256>>>(BT_, C_, C_, 1.f,
            attn, C_, 0, 0,
            Wo_s + (long)l * C_ * C_, C_, 1, 0, 0,
            bo_s + (long)l * C_,
            t, C_, 0, 0,
            1, 1, 0);

        // ======== cross-attention ========
        rmsnorm_k<<<BT_, 256>>>(hidden, g2 + (long)l * C_, hnorm);
        rmsnorm_k<<<BT_, 256>>>(t, g3 + (long)l * C_, xnorm);

        gemm_k<<<gProj, 256>>>(T_, HS_, C_, 1.f,
            xnorm, C_, (long)T_ * C_, 0,
            Wq_x + l * HCHS, HS_, 1, 0, CHS,
            nullptr,
            q, HS_, (long)H_ * THS, THS,
            H_, 0, 0);
        gemm_k<<<gProj, 256>>>(T_, HS_, C_, 1.f,
            hnorm, C_, (long)T_ * C_, 0,
            Wk_x + l * HCHS, HS_, 1, 0, CHS,
            nullptr,
            k, HS_, (long)H_ * THS, THS,
            H_, 0, 0);
        gemm_k<<<gProj, 256>>>(T_, HS_, C_, 1.f,
            hnorm, C_, (long)T_ * C_, 0,
            Wv_x + l * HCHS, HS_, 1, 0, CHS,
            nullptr,
            v, HS_, (long)H_ * THS, THS,
            H_, 0, 0);

        gemm_k<<<gQK, 256>>>(T_, T_, HS_, 0.125f,
            q, HS_, (long)H_ * THS, THS,
            k, 1, HS_, (long)H_ * THS, THS,
            nullptr,
            scores, T_, (long)H_ * TT, TT,
            H_, 0, 0);
        softmax_k<<<gSm, 256>>>(scores, 0);

        gemm_k<<<gPV, 256>>>(T_, HS_, T_, 1.f,
            scores, T_, (long)H_ * TT, TT,
            v, HS_, 1, (long)H_ * THS, THS,
            nullptr,
            attn, C_, (long)T_ * C_, HS_,
            H_, 0, 0);

        gemm_k<<<gO, 256>>>(BT_, C_, C_, 1.f,
            attn, C_, 0, 0,
            Wo_x + (long)l * C_ * C_, C_, 1, 0, 0,
            bo_x + (long)l * C_,
            t, C_, 0, 0,
            1, 1, 0);

        // ======== GELU FFN ========
        rmsnorm_k<<<BT_, 256>>>(t, g4 + (long)l * C_, xnorm);

        gemm_k<<<gF1, 256>>>(BT_, FF_, C_, 1.f,
            xnorm, C_, 0, 0,
            W1 + (long)l * C_ * FF_, FF_, 1, 0, 0,
            b1 + (long)l * FF_,
            ff, FF_, 0, 0,
            1, 0, 1);

        gemm_k<<<gF2, 256>>>(BT_, C_, FF_, 1.f,
            ff, FF_, 0, 0,
            W2 + (long)l * FF_ * C_, C_, 1, 0, 0,
            b2 + (long)l * C_,
            t, C_, 0, 0,
            1, 1, 0);
    }
}

// round 4
// speedup vs baseline: 1.5988x; 1.5988x over previous
#include <cuda_runtime.h>
#include <math.h>

// Problem dims
#define NL  2
#define NB  2
#define T_  2048
#define C_  512
#define H_  8
#define FF_ 1024
#define HS_ 64
#define EPS_ 1.1920929e-07f

#define BT_  (NB * T_)        // 4096 rows
#define BTC_ (NB * T_ * C_)   // 2097152
#define BH_  (NB * H_)        // 16

// ---------------- scratch (device globals; no allocation allowed) ----------------
__device__ float g_xnorm[BTC_];
__device__ float g_hnorm[BTC_];
__device__ float g_q[BTC_];
__device__ float g_k[BTC_];
__device__ float g_v[BTC_];
__device__ float g_attn[BTC_];
__device__ float g_ff[NB * T_ * FF_];
__device__ float g_scores[(size_t)BH_ * T_ * T_];   // 256 MB

// ---------------- helpers ----------------
__global__ void copy_k(float* __restrict__ dst, const float* __restrict__ src, int n) {
    int i = blockIdx.x * blockDim.x + threadIdx.x;
    if (i < n) dst[i] = src[i];
}

// One block per row; C_=512 -> exactly 2 elements per thread at 256 threads.
__global__ __launch_bounds__(256) void rmsnorm_k(
    const float* __restrict__ x, const float* __restrict__ g, float* __restrict__ out)
{
    long row = blockIdx.x;
    const float* xr = x + row * C_;
    float* orow = out + row * C_;
    int tid = threadIdx.x;
    float v0 = xr[tid];
    float v1 = xr[tid + 256];
    float ss = v0 * v0 + v1 * v1;

    __shared__ float red[8];
    #pragma unroll
    for (int o = 16; o; o >>= 1) ss += __shfl_xor_sync(0xffffffffu, ss, o);
    if ((tid & 31) == 0) red[tid >> 5] = ss;
    __syncthreads();
    if (tid == 0) {
        float s = 0.f;
        #pragma unroll
        for (int w = 0; w < 8; w++) s += red[w];
        red[0] = rsqrtf(s * (1.0f / C_) + EPS_);
    }
    __syncthreads();
    float r = red[0];
    orow[tid]       = v0 * r * g[tid];
    orow[tid + 256] = v1 * r * g[tid + 256];
}

// Row softmax over T_ columns; causal: valid length = t+1, tail zeroed.
__global__ __launch_bounds__(256) void softmax_k(float* __restrict__ S, int causal)
{
    long bh = blockIdx.y;
    int t = blockIdx.x;
    float* row = S + (bh * T_ + (long)t) * T_;
    int len = causal ? (t + 1) : T_;
    int tid = threadIdx.x;
    __shared__ float red[8];

    float m = -INFINITY;
    for (int i = tid; i < len; i += 256) m = fmaxf(m, row[i]);
    #pragma unroll
    for (int o = 16; o; o >>= 1) m = fmaxf(m, __shfl_xor_sync(0xffffffffu, m, o));
    if ((tid & 31) == 0) red[tid >> 5] = m;
    __syncthreads();
    if (tid == 0) {
        float mm = red[0];
        #pragma unroll
        for (int w = 1; w < 8; w++) mm = fmaxf(mm, red[w]);
        red[0] = mm;
    }
    __syncthreads();
    m = red[0];
    __syncthreads();

    float s = 0.f;
    for (int i = tid; i < len; i += 256) {
        float e = __expf(row[i] - m);
        row[i] = e;
        s += e;
    }
    #pragma unroll
    for (int o = 16; o; o >>= 1) s += __shfl_xor_sync(0xffffffffu, s, o);
    if ((tid & 31) == 0) red[tid >> 5] = s;
    __syncthreads();
    if (tid == 0) {
        float ss = 0.f;
        #pragma unroll
        for (int w = 0; w < 8; w++) ss += red[w];
        red[0] = ss;
    }
    __syncthreads();
    float inv = 1.0f / red[0];
    for (int i = tid; i < len; i += 256) row[i] *= inv;
    for (int i = tid; i < T_; i += 256) if (i >= len) row[i] = 0.f;
}

// ---------------- TF32 tensor-core GEMM ----------------
__device__ __forceinline__ unsigned f2tf(float x) {
    unsigned u;
    asm("cvt.rna.tf32.f32 %0, %1;" : "=r"(u) : "f"(x));
    return u;
}

__device__ __forceinline__ void mma_tf32(float* d, const unsigned* a, const unsigned* b) {
    asm volatile(
        "mma.sync.aligned.m16n8k8.row.col.f32.tf32.tf32.f32 "
        "{%0,%1,%2,%3}, {%4,%5,%6,%7}, {%8,%9}, {%0,%1,%2,%3};"
        : "+f"(d[0]), "+f"(d[1]), "+f"(d[2]), "+f"(d[3])
        : "r"(a[0]), "r"(a[1]), "r"(a[2]), "r"(a[3]), "r"(b[0]), "r"(b[1]));
}

// C[m,n] (+)= act( alpha * sum_k A[m,k]*B[k,n] + bias[n] )
// Block tile 128x64, BK=16, 256 threads (8 warps, 4x2 grid of 32x32 warp tiles).
// B indexed B[k*ldbk + n*ldbn]. batching via blockIdx.z -> (b,h).
// causal_skip: skip output tiles fully above the diagonal (col0 >= row0+128).
// kcap: limit K to row0+128 (self-attn PV; softmax zeroed the tail).
// M % 128 == 0, N % 64 == 0, K % 16 == 0 for all call sites.
__global__ __launch_bounds__(256) void gemm_tf32(
    int M, int N, int K, float alpha,
    const float* __restrict__ A, int lda, long Ab, long Ah,
    const float* __restrict__ B, int ldbk, int ldbn, long Bb, long Bh,
    const float* __restrict__ bias,
    float* __restrict__ Cp, int ldc, long Cb, long Ch,
    int Hdiv, int accumulate, int gelu_act, int causal_skip, int kcap)
{
    int z = blockIdx.z;
    int b = z / Hdiv, h = z % Hdiv;
    A  += b * Ab + h * Ah;
    B  += b * Bb + h * Bh;
    Cp += b * Cb + h * Ch;

    int row0 = blockIdx.y * 128;
    int col0 = blockIdx.x * 64;
    if (causal_skip && col0 >= row0 + 128) return;
    int Keff = K;
    if (kcap) { int cap = row0 + 128; if (cap < Keff) Keff = cap; }

    __shared__ unsigned As[16][132];
    __shared__ unsigned Bs[16][68];

    int tid = threadIdx.x;
    int lane = tid & 31, w = tid >> 5;
    int g = lane >> 2, t4 = lane & 3;
    int wm = w & 3, wn = w >> 2;

    float acc[2][4][4];
    #pragma unroll
    for (int i = 0; i < 2; i++)
        #pragma unroll
        for (int j = 0; j < 4; j++)
            #pragma unroll
            for (int q = 0; q < 4; q++) acc[i][j][q] = 0.f;

    int arow = tid & 127;
    int akq  = tid >> 7;           // 0 or 1
    int bk   = tid >> 4;           // 0..15
    int bn0  = (tid & 15) * 4;

    float4 aR0, aR1, bR;
    const float* Arow = A + (long)(row0 + arow) * lda;

    // prefetch k0 = 0
    {
        aR0 = *reinterpret_cast<const float4*>(&Arow[akq * 4]);
        aR1 = *reinterpret_cast<const float4*>(&Arow[(akq + 2) * 4]);
        if (ldbn == 1) {
            bR = *reinterpret_cast<const float4*>(&B[(long)bk * ldbk + col0 + bn0]);
        } else {
            const float* bp = &B[(long)bk * ldbk + (long)(col0 + bn0) * ldbn];
            bR.x = bp[0]; bR.y = bp[ldbn]; bR.z = bp[2 * ldbn]; bR.w = bp[3 * ldbn];
        }
    }

    for (int k0 = 0; k0 < Keff; k0 += 16) {
        // stage registers -> smem (with tf32 round)
        As[akq * 4 + 0][arow] = f2tf(aR0.x);
        As[akq * 4 + 1][arow] = f2tf(aR0.y);
        As[akq * 4 + 2][arow] = f2tf(aR0.z);
        As[akq * 4 + 3][arow] = f2tf(aR0.w);
        As[akq * 4 + 8][arow] = f2tf(aR1.x);
        As[akq * 4 + 9][arow] = f2tf(aR1.y);
        As[akq * 4 + 10][arow] = f2tf(aR1.z);
        As[akq * 4 + 11][arow] = f2tf(aR1.w);
        Bs[bk][bn0 + 0] = f2tf(bR.x);
        Bs[bk][bn0 + 1] = f2tf(bR.y);
        Bs[bk][bn0 + 2] = f2tf(bR.z);
        Bs[bk][bn0 + 3] = f2tf(bR.w);
        __syncthreads();

        // prefetch next tile
        if (k0 + 16 < Keff) {
            int kn = k0 + 16;
            aR0 = *reinterpret_cast<const float4*>(&Arow[kn + akq * 4]);
            aR1 = *reinterpret_cast<const float4*>(&Arow[kn + (akq + 2) * 4]);
            if (ldbn == 1) {
                bR = *reinterpret_cast<const float4*>(&B[(long)(kn + bk) * ldbk + col0 + bn0]);
            } else {
                const float* bp = &B[(long)(kn + bk) * ldbk + (long)(col0 + bn0) * ldbn];
                bR.x = bp[0]; bR.y = bp[ldbn]; bR.z = bp[2 * ldbn]; bR.w = bp[3 * ldbn];
            }
        }

        #pragma unroll
        for (int kc = 0; kc < 16; kc += 8) {
            unsigned afr[2][4], bfr[4][2];
            #pragma unroll
            for (int mi = 0; mi < 2; mi++) {
                int m = wm * 32 + mi * 16 + g;
                afr[mi][0] = As[kc + t4][m];
                afr[mi][1] = As[kc + t4][m + 8];
                afr[mi][2] = As[kc + t4 + 4][m];
                afr[mi][3] = As[kc + t4 + 4][m + 8];
            }
            #pragma unroll
            for (int ni = 0; ni < 4; ni++) {
                int n = wn * 32 + ni * 8 + g;
                bfr[ni][0] = Bs[kc + t4][n];
                bfr[ni][1] = Bs[kc + t4 + 4][n];
            }
            #pragma unroll
            for (int mi = 0; mi < 2; mi++)
                #pragma unroll
                for (int ni = 0; ni < 4; ni++)
                    mma_tf32(acc[mi][ni], afr[mi], bfr[ni]);
        }
        __syncthreads();
    }

    // epilogue
    #pragma unroll
    for (int mi = 0; mi < 2; mi++) {
        #pragma unroll
        for (int ni = 0; ni < 4; ni++) {
            int r = row0 + wm * 32 + mi * 16 + g;
            int c = col0 + wn * 32 + ni * 8 + t4 * 2;
            #pragma unroll
            for (int half = 0; half < 2; half++) {
                int rr = r + half * 8;
                float* crow = &Cp[(long)rr * ldc + c];
                #pragma unroll
                for (int jj = 0; jj < 2; jj++) {
                    float vv = alpha * acc[mi][ni][half * 2 + jj];
                    if (bias) vv += bias[c + jj];
                    if (gelu_act) vv = 0.5f * vv * (1.0f + erff(vv * 0.70710678118654752f));
                    if (accumulate) crow[jj] += vv;
                    else            crow[jj]  = vv;
                }
            }
        }
    }
}

// ---------------- orchestration ----------------
extern "C" void kernel_launch(void* const* d_in, const int* in_sizes, int n_in,
                              void* d_out, int out_size)
{
    const float* hidden = (const float*)d_in[0];
    const float* target = (const float*)d_in[1];
    const float* Wq_s = (const float*)d_in[2];
    const float* Wk_s = (const float*)d_in[3];
    const float* Wv_s = (const float*)d_in[4];
    const float* Wo_s = (const float*)d_in[5];
    const float* bo_s = (const float*)d_in[6];
    const float* Wq_x = (const float*)d_in[7];
    const float* Wk_x = (const float*)d_in[8];
    const float* Wv_x = (const float*)d_in[9];
    const float* Wo_x = (const float*)d_in[10];
    const float* bo_x = (const float*)d_in[11];
    const float* W1 = (const float*)d_in[12];
    const float* b1 = (const float*)d_in[13];
    const float* W2 = (const float*)d_in[14];
    const float* b2 = (const float*)d_in[15];
    const float* g1 = (const float*)d_in[16];
    const float* g2 = (const float*)d_in[17];
    const float* g3 = (const float*)d_in[18];
    const float* g4 = (const float*)d_in[19];

    float* t = (float*)d_out;

    float *xnorm, *hnorm, *q, *k, *v, *attn, *ff, *scores;
    cudaGetSymbolAddress((void**)&xnorm, g_xnorm);
    cudaGetSymbolAddress((void**)&hnorm, g_hnorm);
    cudaGetSymbolAddress((void**)&q, g_q);
    cudaGetSymbolAddress((void**)&k, g_k);
    cudaGetSymbolAddress((void**)&v, g_v);
    cudaGetSymbolAddress((void**)&attn, g_attn);
    cudaGetSymbolAddress((void**)&ff, g_ff);
    cudaGetSymbolAddress((void**)&scores, g_scores);

    // t = target
    copy_k<<<(BTC_ + 255) / 256, 256>>>(t, target, BTC_);

    const long HCHS = (long)H_ * C_ * HS_;
    const long CHS  = (long)C_ * HS_;
    const long THS  = (long)T_ * HS_;
    const long TT   = (long)T_ * T_;

    dim3 gProj(1, T_ / 128, BH_);          // N=64, M=2048
    dim3 gQK(T_ / 64, T_ / 128, BH_);      // N=2048, M=2048
    dim3 gPV(1, T_ / 128, BH_);
    dim3 gO(C_ / 64, BT_ / 128, 1);
    dim3 gF1(FF_ / 64, BT_ / 128, 1);
    dim3 gF2(C_ / 64, BT_ / 128, 1);
    dim3 gSm(T_, BH_);

    for (int l = 0; l < NL; l++) {
        // ======== masked self-attention ========
        rmsnorm_k<<<BT_, 256>>>(t, g1 + (long)l * C_, xnorm);

        gemm_tf32<<<gProj, 256>>>(T_, HS_, C_, 1.f,
            xnorm, C_, (long)T_ * C_, 0,
            Wq_s + l * HCHS, HS_, 1, 0, CHS,
            nullptr,
            q, HS_, (long)H_ * THS, THS,
            H_, 0, 0, 0, 0);
        gemm_tf32<<<gProj, 256>>>(T_, HS_, C_, 1.f,
            xnorm, C_, (long)T_ * C_, 0,
            Wk_s + l * HCHS, HS_, 1, 0, CHS,
            nullptr,
            k, HS_, (long)H_ * THS, THS,
            H_, 0, 0, 0, 0);
        gemm_tf32<<<gProj, 256>>>(T_, HS_, C_, 1.f,
            xnorm, C_, (long)T_ * C_, 0,
            Wv_s + l * HCHS, HS_, 1, 0, CHS,
            nullptr,
            v, HS_, (long)H_ * THS, THS,
            H_, 0, 0, 0, 0);

        // S = (Q K^T) * HS^-0.5  (skip fully-masked tiles)
        gemm_tf32<<<gQK, 256>>>(T_, T_, HS_, 0.125f,
            q, HS_, (long)H_ * THS, THS,
            k, 1, HS_, (long)H_ * THS, THS,
            nullptr,
            scores, T_, (long)H_ * TT, TT,
            H_, 0, 0, 1, 0);
        softmax_k<<<gSm, 256>>>(scores, 1);

        // attn = P V  (cap K at row0+128: tail of each row is zero)
        gemm_tf32<<<gPV, 256>>>(T_, HS_, T_, 1.f,
            scores, T_, (long)H_ * TT, TT,
            v, HS_, 1, (long)H_ * THS, THS,
            nullptr,
            attn, C_, (long)T_ * C_, HS_,
            H_, 0, 0, 0, 1);

        // t += attn @ Wo + bo
        gemm_tf32<<<gO, 256>>>(BT_, C_, C_, 1.f,
            attn, C_, 0, 0,
            Wo_s + (long)l * C_ * C_, C_, 1, 0, 0,
            bo_s + (long)l * C_,
            t, C_, 0, 0,
            1, 1, 0, 0, 0);

        // ======== cross-attention ========
        rmsnorm_k<<<BT_, 256>>>(hidden, g2 + (long)l * C_, hnorm);
        rmsnorm_k<<<BT_, 256>>>(t, g3 + (long)l * C_, xnorm);

        gemm_tf32<<<gProj, 256>>>(T_, HS_, C_, 1.f,
            xnorm, C_, (long)T_ * C_, 0,
            Wq_x + l * HCHS, HS_, 1, 0, CHS,
            nullptr,
            q, HS_, (long)H_ * THS, THS,
            H_, 0, 0, 0, 0);
        gemm_tf32<<<gProj, 256>>>(T_, HS_, C_, 1.f,
            hnorm, C_, (long)T_ * C_, 0,
            Wk_x + l * HCHS, HS_, 1, 0, CHS,
            nullptr,
            k, HS_, (long)H_ * THS, THS,
            H_, 0, 0, 0, 0);
        gemm_tf32<<<gProj, 256>>>(T_, HS_, C_, 1.f,
            hnorm, C_, (long)T_ * C_, 0,
            Wv_x + l * HCHS, HS_, 1, 0, CHS,
            nullptr,
            v, HS_, (long)H_ * THS, THS,
            H_, 0, 0, 0, 0);

        gemm_tf32<<<gQK, 256>>>(T_, T_, HS_, 0.125f,
            q, HS_, (long)H_ * THS, THS,
            k, 1, HS_, (long)H_ * THS, THS,
            nullptr,
            scores, T_, (long)H_ * TT, TT,
            H_, 0, 0, 0, 0);
        softmax_k<<<gSm, 256>>>(scores, 0);

        gemm_tf32<<<gPV, 256>>>(T_, HS_, T_, 1.f,
            scores, T_, (long)H_ * TT, TT,
            v, HS_, 1, (long)H_ * THS, THS,
            nullptr,
            attn, C_, (long)T_ * C_, HS_,
            H_, 0, 0, 0, 0);

        gemm_tf32<<<gO, 256>>>(BT_, C_, C_, 1.f,
            attn, C_, 0, 0,
            Wo_x + (long)l * C_ * C_, C_, 1, 0, 0,
            bo_x + (long)l * C_,
            t, C_, 0, 0,
            1, 1, 0, 0, 0);

        // ======== GELU FFN ========
        rmsnorm_k<<<BT_, 256>>>(t, g4 + (long)l * C_, xnorm);

        gemm_tf32<<<gF1, 256>>>(BT_, FF_, C_, 1.f,
            xnorm, C_, 0, 0,
            W1 + (long)l * C_ * FF_, FF_, 1, 0, 0,
            b1 + (long)l * FF_,
            ff, FF_, 0, 0,
            1, 0, 1, 0, 0);

        gemm_tf32<<<gF2, 256>>>(BT_, C_, FF_, 1.f,
            ff, FF_, 0, 0,
            W2 + (long)l * FF_ * C_, C_, 1, 0, 0,
            b2 + (long)l * C_,
            t, C_, 0, 0,
            1, 1, 0, 0, 0);
    }
}

// round 5
// speedup vs baseline: 3.2019x; 2.0026x over previous
#include <cuda_runtime.h>
#include <math.h>

// Problem dims
#define NL  2
#define NB  2
#define T_  2048
#define C_  512
#define H_  8
#define FF_ 1024
#define HS_ 64
#define EPS_ 1.1920929e-07f

#define BT_  (NB * T_)        // 4096 rows
#define BTC_ (NB * T_ * C_)   // 2097152
#define BH_  (NB * H_)        // 16

// ---------------- scratch ----------------
__device__ float g_xnorm[BTC_];
__device__ float g_hnorm[BTC_];
__device__ float g_q[BTC_];      // [B,H,T,HS]
__device__ float g_k[BTC_];
__device__ float g_v[BTC_];
__device__ float g_attn[BTC_];   // [B,T,C]
__device__ float g_ff[NB * T_ * FF_];

// ---------------- helpers ----------------
__global__ void copy_k(float* __restrict__ dst, const float* __restrict__ src, int n) {
    int i = blockIdx.x * blockDim.x + threadIdx.x;
    if (i < n) dst[i] = src[i];
}

__global__ __launch_bounds__(256) void rmsnorm_k(
    const float* __restrict__ x, const float* __restrict__ g, float* __restrict__ out)
{
    long row = blockIdx.x;
    const float* xr = x + row * C_;
    float* orow = out + row * C_;
    int tid = threadIdx.x;
    float v0 = xr[tid];
    float v1 = xr[tid + 256];
    float ss = v0 * v0 + v1 * v1;

    __shared__ float red[8];
    #pragma unroll
    for (int o = 16; o; o >>= 1) ss += __shfl_xor_sync(0xffffffffu, ss, o);
    if ((tid & 31) == 0) red[tid >> 5] = ss;
    __syncthreads();
    if (tid == 0) {
        float s = 0.f;
        #pragma unroll
        for (int w = 0; w < 8; w++) s += red[w];
        red[0] = rsqrtf(s * (1.0f / C_) + EPS_);
    }
    __syncthreads();
    float r = red[0];
    orow[tid]       = v0 * r * g[tid];
    orow[tid + 256] = v1 * r * g[tid + 256];
}

// ---------------- tf32 mma helpers ----------------
__device__ __forceinline__ unsigned f2tf(float x) {
    unsigned u;
    asm("cvt.rna.tf32.f32 %0, %1;" : "=r"(u) : "f"(x));
    return u;
}

__device__ __forceinline__ void mma_tf32(float* d, const unsigned* a, const unsigned* b) {
    asm volatile(
        "mma.sync.aligned.m16n8k8.row.col.f32.tf32.tf32.f32 "
        "{%0,%1,%2,%3}, {%4,%5,%6,%7}, {%8,%9}, {%0,%1,%2,%3};"
        : "+f"(d[0]), "+f"(d[1]), "+f"(d[2]), "+f"(d[3])
        : "r"(a[0]), "r"(a[1]), "r"(a[2]), "r"(a[3]), "r"(b[0]), "r"(b[1]));
}

// ---------------- dense GEMM: 128x128 tile, BK=16, 8 warps of 64x32 ----------------
// A row-major [., K] (lda), per-z offset Ab.
// B: headN==0 -> B[k*ldb + n] ; headN==1 -> B[(n>>6)*Bh + k*HS_ + (n&63)]
// C: headC==0 -> Cp[z*Cb + r*ldc + n] ; headC==1 -> Cp[z*Cb + (n>>6)*Ch + r*HS_ + (n&63)]
__global__ __launch_bounds__(256) void gemm128(
    int K,
    const float* __restrict__ A, int lda, long Ab,
    const float* __restrict__ B, int ldb, long Bh, int headN,
    const float* __restrict__ bias,
    float* __restrict__ Cp, int ldc, long Cb, long Ch, int headC,
    int accumulate, int gelu_act)
{
    int z = blockIdx.z;
    A  += (long)z * Ab;
    Cp += (long)z * Cb;

    int row0 = blockIdx.y * 128;
    int col0 = blockIdx.x * 128;

    __shared__ unsigned As[16][136];
    __shared__ unsigned Bs[16][136];

    int tid = threadIdx.x;
    int lane = tid & 31, w = tid >> 5;
    int g = lane >> 2, t4 = lane & 3;
    int wm = w & 1, wn = w >> 1;           // 2x4 warp grid: 64 rows x 32 cols each

    float acc[4][4][4];
    #pragma unroll
    for (int i = 0; i < 4; i++)
        #pragma unroll
        for (int j = 0; j < 4; j++)
            #pragma unroll
            for (int q = 0; q < 4; q++) acc[i][j][q] = 0.f;

    int arow = tid & 127;
    int ak   = (tid >> 7) * 8;     // 0 or 8
    int bk   = tid >> 4;           // 0..15
    int bn0  = (tid & 15) * 8;

    const float* Arow = A + (long)(row0 + arow) * lda;

    float4 aP0, aP1, bP0, bP1;
    // prefetch k0=0
    aP0 = *reinterpret_cast<const float4*>(&Arow[ak]);
    aP1 = *reinterpret_cast<const float4*>(&Arow[ak + 4]);
    if (headN) {
        const float* bp = &B[(long)((col0 + bn0) >> 6) * Bh + (long)bk * HS_ + ((col0 + bn0) & 63)];
        bP0 = *reinterpret_cast<const float4*>(bp);
        bP1 = *reinterpret_cast<const float4*>(bp + 4);
    } else {
        const float* bp = &B[(long)bk * ldb + col0 + bn0];
        bP0 = *reinterpret_cast<const float4*>(bp);
        bP1 = *reinterpret_cast<const float4*>(bp + 4);
    }

    for (int k0 = 0; k0 < K; k0 += 16) {
        As[ak + 0][arow] = f2tf(aP0.x);
        As[ak + 1][arow] = f2tf(aP0.y);
        As[ak + 2][arow] = f2tf(aP0.z);
        As[ak + 3][arow] = f2tf(aP0.w);
        As[ak + 4][arow] = f2tf(aP1.x);
        As[ak + 5][arow] = f2tf(aP1.y);
        As[ak + 6][arow] = f2tf(aP1.z);
        As[ak + 7][arow] = f2tf(aP1.w);
        {
            uint4 u0 = {f2tf(bP0.x), f2tf(bP0.y), f2tf(bP0.z), f2tf(bP0.w)};
            uint4 u1 = {f2tf(bP1.x), f2tf(bP1.y), f2tf(bP1.z), f2tf(bP1.w)};
            *reinterpret_cast<uint4*>(&Bs[bk][bn0])     = u0;
            *reinterpret_cast<uint4*>(&Bs[bk][bn0 + 4]) = u1;
        }
        __syncthreads();

        if (k0 + 16 < K) {
            int kn = k0 + 16;
            aP0 = *reinterpret_cast<const float4*>(&Arow[kn + ak]);
            aP1 = *reinterpret_cast<const float4*>(&Arow[kn + ak + 4]);
            if (headN) {
                const float* bp = &B[(long)((col0 + bn0) >> 6) * Bh + (long)(kn + bk) * HS_ + ((col0 + bn0) & 63)];
                bP0 = *reinterpret_cast<const float4*>(bp);
                bP1 = *reinterpret_cast<const float4*>(bp + 4);
            } else {
                const float* bp = &B[(long)(kn + bk) * ldb + col0 + bn0];
                bP0 = *reinterpret_cast<const float4*>(bp);
                bP1 = *reinterpret_cast<const float4*>(bp + 4);
            }
        }

        #pragma unroll
        for (int kc = 0; kc < 16; kc += 8) {
            unsigned afr[4][4], bfr[4][2];
            #pragma unroll
            for (int mi = 0; mi < 4; mi++) {
                int m = wm * 64 + mi * 16 + g;
                afr[mi][0] = As[kc + t4][m];
                afr[mi][1] = As[kc + t4][m + 8];
                afr[mi][2] = As[kc + t4 + 4][m];
                afr[mi][3] = As[kc + t4 + 4][m + 8];
            }
            #pragma unroll
            for (int ni = 0; ni < 4; ni++) {
                int n = wn * 32 + ni * 8 + g;
                bfr[ni][0] = Bs[kc + t4][n];
                bfr[ni][1] = Bs[kc + t4 + 4][n];
            }
            #pragma unroll
            for (int mi = 0; mi < 4; mi++)
                #pragma unroll
                for (int ni = 0; ni < 4; ni++)
                    mma_tf32(acc[mi][ni], afr[mi], bfr[ni]);
        }
        __syncthreads();
    }

    // epilogue
    #pragma unroll
    for (int mi = 0; mi < 4; mi++) {
        #pragma unroll
        for (int ni = 0; ni < 4; ni++) {
            int r0 = row0 + wm * 64 + mi * 16 + g;
            int c  = col0 + wn * 32 + ni * 8 + t4 * 2;
            #pragma unroll
            for (int half = 0; half < 2; half++) {
                int rr = r0 + half * 8;
                float* crow;
                if (headC) crow = &Cp[(long)(c >> 6) * Ch + (long)rr * HS_ + (c & 63)];
                else       crow = &Cp[(long)rr * ldc + c];
                #pragma unroll
                for (int jj = 0; jj < 2; jj++) {
                    float vv = acc[mi][ni][half * 2 + jj];
                    if (bias) vv += bias[c + jj];
                    if (gelu_act) vv = 0.5f * vv * (1.0f + erff(vv * 0.70710678118654752f));
                    if (accumulate) crow[jj] += vv;
                    else            crow[jj]  = vv;
                }
            }
        }
    }
}

// ---------------- fused flash attention (tf32 mma, online softmax) ----------------
// Q,K,V: [B,H,T,HS] fp32.  Out: [B,T,C] fp32 (heads concatenated).
// Block: 128 Q rows, 8 warps x 16 rows. KV streamed in 64-wide tiles.
// Dynamic smem: Ks[64][68] + Vs[64][72] + Ps[128][68] (unsigned/tf32) = 70656 B.
#define FLASH_SMEM ((64*68 + 64*72 + 128*68) * 4)

__global__ __launch_bounds__(256) void flash_k(
    const float* __restrict__ Qg,
    const float* __restrict__ Kg,
    const float* __restrict__ Vg,
    float* __restrict__ Out,
    int causal)
{
    extern __shared__ unsigned sh[];
    unsigned (*Ks)[68] = reinterpret_cast<unsigned(*)[68]>(sh);
    unsigned (*Vs)[72] = reinterpret_cast<unsigned(*)[72]>(sh + 64 * 68);
    unsigned (*Ps)[68] = reinterpret_cast<unsigned(*)[68]>(sh + 64 * 68 + 64 * 72);

    int bh = blockIdx.y;
    int b = bh >> 3, h = bh & 7;
    int q0 = blockIdx.x * 128;
    long base = (long)bh * T_ * HS_;
    const float* Qb = Qg + base;
    const float* Kb = Kg + base;
    const float* Vb = Vg + base;

    int tid = threadIdx.x;
    int lane = tid & 31, w = tid >> 5;
    int g = lane >> 2, t4 = lane & 3;
    int wr = w * 16;

    // Q fragments (held for whole block)
    unsigned Qa[8][4];
    {
        const float* q0p = Qb + (long)(q0 + wr + g) * HS_;
        const float* q1p = Qb + (long)(q0 + wr + g + 8) * HS_;
        #pragma unroll
        for (int kk = 0; kk < 8; kk++) {
            Qa[kk][0] = f2tf(q0p[kk * 8 + t4]);
            Qa[kk][1] = f2tf(q1p[kk * 8 + t4]);
            Qa[kk][2] = f2tf(q0p[kk * 8 + t4 + 4]);
            Qa[kk][3] = f2tf(q1p[kk * 8 + t4 + 4]);
        }
    }

    float Oacc[8][4];
    #pragma unroll
    for (int i = 0; i < 8; i++)
        #pragma unroll
        for (int j = 0; j < 4; j++) Oacc[i][j] = 0.f;
    float m0 = -1e30f, m1 = -1e30f, l0 = 0.f, l1 = 0.f;

    int s_end = causal ? (q0 + 128) : T_;

    for (int s0 = 0; s0 < s_end; s0 += 64) {
        __syncthreads();
        // cooperative K/V tile load (64x64 each)
        {
            int r = tid >> 2;
            int c0 = (tid & 3) * 16;
            const float* kp = Kb + (long)(s0 + r) * HS_ + c0;
            const float* vp = Vb + (long)(s0 + r) * HS_ + c0;
            #pragma unroll
            for (int j = 0; j < 4; j++) {
                float4 kv = *reinterpret_cast<const float4*>(kp + j * 4);
                Ks[r][c0 + j * 4 + 0] = f2tf(kv.x);
                Ks[r][c0 + j * 4 + 1] = f2tf(kv.y);
                Ks[r][c0 + j * 4 + 2] = f2tf(kv.z);
                Ks[r][c0 + j * 4 + 3] = f2tf(kv.w);
                float4 vv = *reinterpret_cast<const float4*>(vp + j * 4);
                Vs[r][c0 + j * 4 + 0] = f2tf(vv.x);
                Vs[r][c0 + j * 4 + 1] = f2tf(vv.y);
                Vs[r][c0 + j * 4 + 2] = f2tf(vv.z);
                Vs[r][c0 + j * 4 + 3] = f2tf(vv.w);
            }
        }
        __syncthreads();

        // S = (Q K^T) * 0.125
        float S[8][4];
        #pragma unroll
        for (int nf = 0; nf < 8; nf++)
            #pragma unroll
            for (int j = 0; j < 4; j++) S[nf][j] = 0.f;

        #pragma unroll
        for (int kk = 0; kk < 8; kk++) {
            #pragma unroll
            for (int nf = 0; nf < 8; nf++) {
                unsigned b2[2];
                b2[0] = Ks[nf * 8 + g][kk * 8 + t4];
                b2[1] = Ks[nf * 8 + g][kk * 8 + t4 + 4];
                mma_tf32(S[nf], Qa[kk], b2);
            }
        }
        #pragma unroll
        for (int nf = 0; nf < 8; nf++)
            #pragma unroll
            for (int j = 0; j < 4; j++) S[nf][j] *= 0.125f;

        // causal mask (diagonal tiles only)
        if (causal && (s0 + 63 > q0 + wr)) {
            int r0g = q0 + wr + g;
            #pragma unroll
            for (int nf = 0; nf < 8; nf++) {
                int cbase = s0 + nf * 8 + 2 * t4;
                if (cbase     > r0g)     S[nf][0] = -1e30f;
                if (cbase + 1 > r0g)     S[nf][1] = -1e30f;
                if (cbase     > r0g + 8) S[nf][2] = -1e30f;
                if (cbase + 1 > r0g + 8) S[nf][3] = -1e30f;
            }
        }

        // row max (reduce over t4 quad)
        float tm0 = -1e30f, tm1 = -1e30f;
        #pragma unroll
        for (int nf = 0; nf < 8; nf++) {
            tm0 = fmaxf(tm0, fmaxf(S[nf][0], S[nf][1]));
            tm1 = fmaxf(tm1, fmaxf(S[nf][2], S[nf][3]));
        }
        tm0 = fmaxf(tm0, __shfl_xor_sync(0xffffffffu, tm0, 1));
        tm0 = fmaxf(tm0, __shfl_xor_sync(0xffffffffu, tm0, 2));
        tm1 = fmaxf(tm1, __shfl_xor_sync(0xffffffffu, tm1, 1));
        tm1 = fmaxf(tm1, __shfl_xor_sync(0xffffffffu, tm1, 2));

        float nm0 = fmaxf(m0, tm0), nm1 = fmaxf(m1, tm1);
        float f0 = __expf(m0 - nm0), f1 = __expf(m1 - nm1);

        float rs0 = 0.f, rs1 = 0.f;
        #pragma unroll
        for (int nf = 0; nf < 8; nf++) {
            float p0 = __expf(S[nf][0] - nm0);
            float p1 = __expf(S[nf][1] - nm0);
            float p2 = __expf(S[nf][2] - nm1);
            float p3 = __expf(S[nf][3] - nm1);
            rs0 += p0 + p1;
            rs1 += p2 + p3;
            int cb = nf * 8 + 2 * t4;
            Ps[wr + g][cb]         = f2tf(p0);
            Ps[wr + g][cb + 1]     = f2tf(p1);
            Ps[wr + g + 8][cb]     = f2tf(p2);
            Ps[wr + g + 8][cb + 1] = f2tf(p3);
        }
        rs0 += __shfl_xor_sync(0xffffffffu, rs0, 1);
        rs0 += __shfl_xor_sync(0xffffffffu, rs0, 2);
        rs1 += __shfl_xor_sync(0xffffffffu, rs1, 1);
        rs1 += __shfl_xor_sync(0xffffffffu, rs1, 2);

        l0 = l0 * f0 + rs0;
        l1 = l1 * f1 + rs1;
        m0 = nm0; m1 = nm1;

        #pragma unroll
        for (int nf = 0; nf < 8; nf++) {
            Oacc[nf][0] *= f0; Oacc[nf][1] *= f0;
            Oacc[nf][2] *= f1; Oacc[nf][3] *= f1;
        }

        __syncwarp();

        // O += P V
        #pragma unroll
        for (int kk = 0; kk < 8; kk++) {
            unsigned a4[4];
            a4[0] = Ps[wr + g][kk * 8 + t4];
            a4[1] = Ps[wr + g + 8][kk * 8 + t4];
            a4[2] = Ps[wr + g][kk * 8 + t4 + 4];
            a4[3] = Ps[wr + g + 8][kk * 8 + t4 + 4];
            #pragma unroll
            for (int nf = 0; nf < 8; nf++) {
                unsigned b2[2];
                b2[0] = Vs[kk * 8 + t4][nf * 8 + g];
                b2[1] = Vs[kk * 8 + t4 + 4][nf * 8 + g];
                mma_tf32(Oacc[nf], a4, b2);
            }
        }
    }

    // epilogue: normalize and write [B,T,C]
    float inv0 = 1.f / l0, inv1 = 1.f / l1;
    float* o0 = Out + ((long)b * T_ + q0 + wr + g) * C_ + h * HS_;
    float* o1 = Out + ((long)b * T_ + q0 + wr + g + 8) * C_ + h * HS_;
    #pragma unroll
    for (int nf = 0; nf < 8; nf++) {
        int c = nf * 8 + 2 * t4;
        float2 v0 = {Oacc[nf][0] * inv0, Oacc[nf][1] * inv0};
        float2 v1 = {Oacc[nf][2] * inv1, Oacc[nf][3] * inv1};
        *reinterpret_cast<float2*>(o0 + c) = v0;
        *reinterpret_cast<float2*>(o1 + c) = v1;
    }
}

// ---------------- orchestration ----------------
extern "C" void kernel_launch(void* const* d_in, const int* in_sizes, int n_in,
                              void* d_out, int out_size)
{
    const float* hidden = (const float*)d_in[0];
    const float* target = (const float*)d_in[1];
    const float* Wq_s = (const float*)d_in[2];
    const float* Wk_s = (const float*)d_in[3];
    const float* Wv_s = (const float*)d_in[4];
    const float* Wo_s = (const float*)d_in[5];
    const float* bo_s = (const float*)d_in[6];
    const float* Wq_x = (const float*)d_in[7];
    const float* Wk_x = (const float*)d_in[8];
    const float* Wv_x = (const float*)d_in[9];
    const float* Wo_x = (const float*)d_in[10];
    const float* bo_x = (const float*)d_in[11];
    const float* W1 = (const float*)d_in[12];
    const float* b1 = (const float*)d_in[13];
    const float* W2 = (const float*)d_in[14];
    const float* b2 = (const float*)d_in[15];
    const float* g1 = (const float*)d_in[16];
    const float* g2 = (const float*)d_in[17];
    const float* g3 = (const float*)d_in[18];
    const float* g4 = (const float*)d_in[19];

    float* t = (float*)d_out;

    float *xnorm, *hnorm, *q, *k, *v, *attn, *ff;
    cudaGetSymbolAddress((void**)&xnorm, g_xnorm);
    cudaGetSymbolAddress((void**)&hnorm, g_hnorm);
    cudaGetSymbolAddress((void**)&q, g_q);
    cudaGetSymbolAddress((void**)&k, g_k);
    cudaGetSymbolAddress((void**)&v, g_v);
    cudaGetSymbolAddress((void**)&attn, g_attn);
    cudaGetSymbolAddress((void**)&ff, g_ff);

    cudaFuncSetAttribute(flash_k, cudaFuncAttributeMaxDynamicSharedMemorySize, FLASH_SMEM);

    copy_k<<<(BTC_ + 255) / 256, 256>>>(t, target, BTC_);

    const long HCHS = (long)H_ * C_ * HS_;   // per-layer weight stride
    const long CHS  = (long)C_ * HS_;        // per-head weight stride
    const long BHT  = (long)H_ * T_ * HS_;   // per-b stride of q/k/v

    dim3 gProj(C_ / 128, T_ / 128, NB);      // N=512, M=2048, z=b
    dim3 gO(C_ / 128, BT_ / 128, 1);
    dim3 gF1(FF_ / 128, BT_ / 128, 1);
    dim3 gF2(C_ / 128, BT_ / 128, 1);
    dim3 gFl(T_ / 128, BH_, 1);

    for (int l = 0; l < NL; l++) {
        // ======== masked self-attention ========
        rmsnorm_k<<<BT_, 256>>>(t, g1 + (long)l * C_, xnorm);

        gemm128<<<gProj, 256>>>(C_,
            xnorm, C_, (long)T_ * C_,
            Wq_s + l * HCHS, 0, CHS, 1,
            nullptr,
            q, 0, BHT, (long)T_ * HS_, 1, 0, 0);
        gemm128<<<gProj, 256>>>(C_,
            xnorm, C_, (long)T_ * C_,
            Wk_s + l * HCHS, 0, CHS, 1,
            nullptr,
            k, 0, BHT, (long)T_ * HS_, 1, 0, 0);
        gemm128<<<gProj, 256>>>(C_,
            xnorm, C_, (long)T_ * C_,
            Wv_s + l * HCHS, 0, CHS, 1,
            nullptr,
            v, 0, BHT, (long)T_ * HS_, 1, 0, 0);

        flash_k<<<gFl, 256, FLASH_SMEM>>>(q, k, v, attn, 1);

        gemm128<<<gO, 256>>>(C_,
            attn, C_, 0,
            Wo_s + (long)l * C_ * C_, C_, 0, 0,
            bo_s + (long)l * C_,
            t, C_, 0, 0, 0, 1, 0);

        // ======== cross-attention ========
        rmsnorm_k<<<BT_, 256>>>(hidden, g2 + (long)l * C_, hnorm);
        rmsnorm_k<<<BT_, 256>>>(t, g3 + (long)l * C_, xnorm);

        gemm128<<<gProj, 256>>>(C_,
            xnorm, C_, (long)T_ * C_,
            Wq_x + l * HCHS, 0, CHS, 1,
            nullptr,
            q, 0, BHT, (long)T_ * HS_, 1, 0, 0);
        gemm128<<<gProj, 256>>>(C_,
            hnorm, C_, (long)T_ * C_,
            Wk_x + l * HCHS, 0, CHS, 1,
            nullptr,
            k, 0, BHT, (long)T_ * HS_, 1, 0, 0);
        gemm128<<<gProj, 256>>>(C_,
            hnorm, C_, (long)T_ * C_,
            Wv_x + l * HCHS, 0, CHS, 1,
            nullptr,
            v, 0, BHT, (long)T_ * HS_, 1, 0, 0);

        flash_k<<<gFl, 256, FLASH_SMEM>>>(q, k, v, attn, 0);

        gemm128<<<gO, 256>>>(C_,
            attn, C_, 0,
            Wo_x + (long)l * C_ * C_, C_, 0, 0,
            bo_x + (long)l * C_,
            t, C_, 0, 0, 0, 1, 0);

        // ======== GELU FFN ========
        rmsnorm_k<<<BT_, 256>>>(t, g4 + (long)l * C_, xnorm);

        gemm128<<<gF1, 256>>>(C_,
            xnorm, C_, 0,
            W1 + (long)l * C_ * FF_, FF_, 0, 0,
            b1 + (long)l * FF_,
            ff, FF_, 0, 0, 0, 0, 1);

        gemm128<<<gF2, 256>>>(FF_,
            ff, FF_, 0,
            W2 + (long)l * FF_ * C_, C_, 0, 0,
            b2 + (long)l * C_,
            t, C_, 0, 0, 0, 1, 0);
    }
}

// round 6
// speedup vs baseline: 4.3273x; 1.3515x over previous
#include <cuda_runtime.h>
#include <math.h>

// Problem dims
#define NL  2
#define NB  2
#define T_  2048
#define C_  512
#define H_  8
#define FF_ 1024
#define HS_ 64
#define EPS_ 1.1920929e-07f

#define BT_  (NB * T_)        // 4096 rows
#define BTC_ (NB * T_ * C_)   // 2097152
#define BH_  (NB * H_)        // 16

// ---------------- scratch ----------------
__device__ float g_xnorm[BTC_];
__device__ float g_hnorm[BTC_];
__device__ float g_q[BTC_];      // [B,H,T,HS]
__device__ float g_k[BTC_];
__device__ float g_v[BTC_];
__device__ float g_attn[BTC_];   // [B,T,C]
__device__ float g_ff[NB * T_ * FF_];

// ---------------- cp.async helpers ----------------
__device__ __forceinline__ unsigned sm_u32(const void* p) {
    return (unsigned)__cvta_generic_to_shared(p);
}
__device__ __forceinline__ void cp16(void* dst_smem, const void* src) {
    asm volatile("cp.async.cg.shared.global [%0], [%1], 16;"
                 :: "r"(sm_u32(dst_smem)), "l"(src));
}
#define CP_COMMIT() asm volatile("cp.async.commit_group;")
#define CP_WAIT(n)  asm volatile("cp.async.wait_group %0;" :: "n"(n))

// ---------------- helpers ----------------
__global__ void copy_k(float4* __restrict__ dst, const float4* __restrict__ src, int n4) {
    int i = blockIdx.x * blockDim.x + threadIdx.x;
    if (i < n4) dst[i] = src[i];
}

__global__ __launch_bounds__(256) void rmsnorm_k(
    const float* __restrict__ x, const float* __restrict__ g, float* __restrict__ out)
{
    long row = blockIdx.x;
    const float* xr = x + row * C_;
    float* orow = out + row * C_;
    int tid = threadIdx.x;
    float v0 = xr[tid];
    float v1 = xr[tid + 256];
    float ss = v0 * v0 + v1 * v1;

    __shared__ float red[8];
    #pragma unroll
    for (int o = 16; o; o >>= 1) ss += __shfl_xor_sync(0xffffffffu, ss, o);
    if ((tid & 31) == 0) red[tid >> 5] = ss;
    __syncthreads();
    if (tid == 0) {
        float s = 0.f;
        #pragma unroll
        for (int w = 0; w < 8; w++) s += red[w];
        red[0] = rsqrtf(s * (1.0f / C_) + EPS_);
    }
    __syncthreads();
    float r = red[0];
    orow[tid]       = v0 * r * g[tid];
    orow[tid + 256] = v1 * r * g[tid + 256];
}

// ---------------- tf32 mma (raw fp32 bits -> tf32 truncation) ----------------
__device__ __forceinline__ void mma_tf32(float* d, const unsigned* a, const unsigned* b) {
    asm volatile(
        "mma.sync.aligned.m16n8k8.row.col.f32.tf32.tf32.f32 "
        "{%0,%1,%2,%3}, {%4,%5,%6,%7}, {%8,%9}, {%0,%1,%2,%3};"
        : "+f"(d[0]), "+f"(d[1]), "+f"(d[2]), "+f"(d[3])
        : "r"(a[0]), "r"(a[1]), "r"(a[2]), "r"(a[3]), "r"(b[0]), "r"(b[1]));
}
__device__ __forceinline__ unsigned fbits(float x) { return __float_as_uint(x); }

// ---------------- dense GEMM: 128x128 tile, BK=16, cp.async 2-stage ----------------
// A row-major [., K] (lda), per-z offset Ab. smem As kept row-major [row][k].
// B select (QKV fusion): sel = blockIdx.x / nColBlk picks B0/B1/B2 and C0/C1/C2.
// B: headN==0 -> B[k*ldb + n] ; headN==1 -> B[(n>>6)*Bh + k*HS_ + (n&63)]
// C: headC==0 -> C[z*Cb + r*ldc + n] ; headC==1 -> C[z*Cb + (n>>6)*Ch + r*HS_ + (n&63)]
#define ASTR 20
#define BSTR 136
__global__ __launch_bounds__(256) void gemm128(
    int K,
    const float* __restrict__ A, int lda, long Ab,
    const float* __restrict__ B0, const float* __restrict__ B1, const float* __restrict__ B2,
    int ldb, long Bh, int headN,
    const float* __restrict__ bias,
    float* __restrict__ C0, float* __restrict__ C1, float* __restrict__ C2,
    int ldc, long Cb, long Ch, int headC,
    int accumulate, int gelu_act, int nColBlk)
{
    __shared__ float As[2][128 * ASTR];
    __shared__ float Bs[2][16 * BSTR];

    int sel  = blockIdx.x / nColBlk;
    int colb = blockIdx.x - sel * nColBlk;
    const float* B = (sel == 0) ? B0 : (sel == 1) ? B1 : B2;
    float* Cp      = (sel == 0) ? C0 : (sel == 1) ? C1 : C2;

    int z = blockIdx.z;
    A  += (long)z * Ab;
    Cp += (long)z * Cb;

    int row0 = blockIdx.y * 128;
    int col0 = colb * 128;

    int tid = threadIdx.x;
    int lane = tid & 31, w = tid >> 5;
    int g = lane >> 2, t4 = lane & 3;
    int wm = w & 1, wn = w >> 1;           // 2x4 warp grid: 64 rows x 32 cols

    float acc[4][4][4];
    #pragma unroll
    for (int i = 0; i < 4; i++)
        #pragma unroll
        for (int j = 0; j < 4; j++)
            #pragma unroll
            for (int q = 0; q < 4; q++) acc[i][j][q] = 0.f;

    // A tile: 128 rows x 16 k = 512 chunks of 16B; 2 per thread.
    // B tile: 16 k x 128 n   = 512 chunks; 2 per thread.
    int acRow0 = (tid * 2) >> 2;           // both chunks same row (c, c+1 share row since 4 chunks/row, tid*2 even)
    int acK0   = ((tid * 2) & 3) * 4;
    int bcK    = (tid * 2) >> 5;
    int bcN0   = ((tid * 2) & 31) * 4;

    const float* Abase = A + (long)row0 * lda;

    auto issue = [&](int st, int k0) {
        // A chunks
        #pragma unroll
        for (int j = 0; j < 2; j++) {
            int row = acRow0;              // tid*2 and tid*2+1: rows equal ((tid*2)>>2 == (tid*2+1)>>2 when (tid*2)&3 < 3)
            int kc  = acK0 + j * 4;
            int c   = tid * 2 + j;
            row = c >> 2; kc = (c & 3) * 4;
            cp16(&As[st][row * ASTR + kc], Abase + (long)row * lda + k0 + kc);
        }
        // B chunks
        #pragma unroll
        for (int j = 0; j < 2; j++) {
            int c  = tid * 2 + j;
            int kk = c >> 5;
            int n4 = (c & 31) * 4;
            const float* gp;
            if (headN) {
                int gc = col0 + n4;
                gp = &B[(long)(gc >> 6) * Bh + (long)(k0 + kk) * HS_ + (gc & 63)];
            } else {
                gp = &B[(long)(k0 + kk) * ldb + col0 + n4];
            }
            cp16(&Bs[st][kk * BSTR + n4], gp);
        }
    };

    int nK = K >> 4;
    issue(0, 0);
    CP_COMMIT();

    for (int kt = 0; kt < nK; kt++) {
        int s = kt & 1;
        if (kt + 1 < nK) {
            issue(s ^ 1, (kt + 1) * 16);
            CP_COMMIT();
            CP_WAIT(1);
        } else {
            CP_WAIT(0);
        }
        __syncthreads();

        #pragma unroll
        for (int kc = 0; kc < 16; kc += 8) {
            unsigned afr[4][4], bfr[4][2];
            #pragma unroll
            for (int mi = 0; mi < 4; mi++) {
                int m = wm * 64 + mi * 16 + g;
                afr[mi][0] = fbits(As[s][m * ASTR + kc + t4]);
                afr[mi][1] = fbits(As[s][(m + 8) * ASTR + kc + t4]);
                afr[mi][2] = fbits(As[s][m * ASTR + kc + t4 + 4]);
                afr[mi][3] = fbits(As[s][(m + 8) * ASTR + kc + t4 + 4]);
            }
            #pragma unroll
            for (int ni = 0; ni < 4; ni++) {
                int n = wn * 32 + ni * 8 + g;
                bfr[ni][0] = fbits(Bs[s][(kc + t4) * BSTR + n]);
                bfr[ni][1] = fbits(Bs[s][(kc + t4 + 4) * BSTR + n]);
            }
            #pragma unroll
            for (int mi = 0; mi < 4; mi++)
                #pragma unroll
                for (int ni = 0; ni < 4; ni++)
                    mma_tf32(acc[mi][ni], afr[mi], bfr[ni]);
        }
        __syncthreads();
    }

    // epilogue
    #pragma unroll
    for (int mi = 0; mi < 4; mi++) {
        #pragma unroll
        for (int ni = 0; ni < 4; ni++) {
            int r0 = row0 + wm * 64 + mi * 16 + g;
            int c  = col0 + wn * 32 + ni * 8 + t4 * 2;
            #pragma unroll
            for (int half = 0; half < 2; half++) {
                int rr = r0 + half * 8;
                float* crow;
                if (headC) crow = &Cp[(long)(c >> 6) * Ch + (long)rr * HS_ + (c & 63)];
                else       crow = &Cp[(long)rr * ldc + c];
                #pragma unroll
                for (int jj = 0; jj < 2; jj++) {
                    float vv = acc[mi][ni][half * 2 + jj];
                    if (bias) vv += bias[c + jj];
                    if (gelu_act) vv = 0.5f * vv * (1.0f + erff(vv * 0.70710678118654752f));
                    if (accumulate) crow[jj] += vv;
                    else            crow[jj]  = vv;
                }
            }
        }
    }
}

// ---------------- fused flash attention (tf32 mma, online softmax, cp.async 2-stage KV) ----------------
// Q,K,V: [B,H,T,HS] fp32.  Out: [B,T,C] fp32 (heads concatenated).
// Block: 128 Q rows, 8 warps x 16 rows. KV streamed in 64-wide tiles, double-buffered.
// Dyn smem: Ks[2][64][68] + Vs[2][64][72] + Ps[128][68] floats = 106496 B.
#define KS_W 68
#define VS_W 72
#define PS_W 68
#define FLASH_SMEM ((2*64*KS_W + 2*64*VS_W + 128*PS_W) * 4)

__global__ __launch_bounds__(256) void flash_k(
    const float* __restrict__ Qg,
    const float* __restrict__ Kg,
    const float* __restrict__ Vg,
    float* __restrict__ Out,
    int causal)
{
    extern __shared__ float sh[];
    float* KsB = sh;                               // [2][64*KS_W]
    float* VsB = sh + 2 * 64 * KS_W;               // [2][64*VS_W]
    float* Ps  = sh + 2 * 64 * KS_W + 2 * 64 * VS_W; // [128*PS_W]

    int bh = blockIdx.y;
    int b = bh >> 3, h = bh & 7;
    int q0 = blockIdx.x * 128;
    long base = (long)bh * T_ * HS_;
    const float* Qb = Qg + base;
    const float* Kb = Kg + base;
    const float* Vb = Vg + base;

    int tid = threadIdx.x;
    int lane = tid & 31, w = tid >> 5;
    int g = lane >> 2, t4 = lane & 3;
    int wr = w * 16;

    auto loadKV = [&](int st, int s0) {
        #pragma unroll
        for (int j = 0; j < 4; j++) {
            int c = tid + j * 256;
            int row = c >> 4;
            int cc = (c & 15) * 4;
            cp16(&KsB[st * 64 * KS_W + row * KS_W + cc], Kb + (long)(s0 + row) * HS_ + cc);
            cp16(&VsB[st * 64 * VS_W + row * VS_W + cc], Vb + (long)(s0 + row) * HS_ + cc);
        }
    };

    // Q fragments (raw fp32 bits), held for the whole block
    unsigned Qa[8][4];
    {
        const float* q0p = Qb + (long)(q0 + wr + g) * HS_;
        const float* q1p = Qb + (long)(q0 + wr + g + 8) * HS_;
        #pragma unroll
        for (int kk = 0; kk < 8; kk++) {
            Qa[kk][0] = fbits(q0p[kk * 8 + t4]);
            Qa[kk][1] = fbits(q1p[kk * 8 + t4]);
            Qa[kk][2] = fbits(q0p[kk * 8 + t4 + 4]);
            Qa[kk][3] = fbits(q1p[kk * 8 + t4 + 4]);
        }
    }

    float Oacc[8][4];
    #pragma unroll
    for (int i = 0; i < 8; i++)
        #pragma unroll
        for (int j = 0; j < 4; j++) Oacc[i][j] = 0.f;
    float m0 = -1e30f, m1 = -1e30f, l0 = 0.f, l1 = 0.f;

    int nT = causal ? (q0 / 64 + 2) : (T_ / 64);

    loadKV(0, 0);
    CP_COMMIT();

    for (int it = 0; it < nT; it++) {
        int s = it & 1;
        int s0 = it * 64;
        if (it + 1 < nT) {
            loadKV(s ^ 1, (it + 1) * 64);
            CP_COMMIT();
            CP_WAIT(1);
        } else {
            CP_WAIT(0);
        }
        __syncthreads();

        const float* Ks = KsB + s * 64 * KS_W;
        const float* Vs = VsB + s * 64 * VS_W;

        // S = (Q K^T) * 0.125
        float S[8][4];
        #pragma unroll
        for (int nf = 0; nf < 8; nf++)
            #pragma unroll
            for (int j = 0; j < 4; j++) S[nf][j] = 0.f;

        #pragma unroll
        for (int kk = 0; kk < 8; kk++) {
            #pragma unroll
            for (int nf = 0; nf < 8; nf++) {
                unsigned b2[2];
                b2[0] = fbits(Ks[(nf * 8 + g) * KS_W + kk * 8 + t4]);
                b2[1] = fbits(Ks[(nf * 8 + g) * KS_W + kk * 8 + t4 + 4]);
                mma_tf32(S[nf], Qa[kk], b2);
            }
        }
        #pragma unroll
        for (int nf = 0; nf < 8; nf++)
            #pragma unroll
            for (int j = 0; j < 4; j++) S[nf][j] *= 0.125f;

        // causal mask (diagonal tiles only)
        if (causal && (s0 + 63 > q0 + wr)) {
            int r0g = q0 + wr + g;
            #pragma unroll
            for (int nf = 0; nf < 8; nf++) {
                int cbase = s0 + nf * 8 + 2 * t4;
                if (cbase     > r0g)     S[nf][0] = -1e30f;
                if (cbase + 1 > r0g)     S[nf][1] = -1e30f;
                if (cbase     > r0g + 8) S[nf][2] = -1e30f;
                if (cbase + 1 > r0g + 8) S[nf][3] = -1e30f;
            }
        }

        // row max (reduce over t4 quad)
        float tm0 = -1e30f, tm1 = -1e30f;
        #pragma unroll
        for (int nf = 0; nf < 8; nf++) {
            tm0 = fmaxf(tm0, fmaxf(S[nf][0], S[nf][1]));
            tm1 = fmaxf(tm1, fmaxf(S[nf][2], S[nf][3]));
        }
        tm0 = fmaxf(tm0, __shfl_xor_sync(0xffffffffu, tm0, 1));
        tm0 = fmaxf(tm0, __shfl_xor_sync(0xffffffffu, tm0, 2));
        tm1 = fmaxf(tm1, __shfl_xor_sync(0xffffffffu, tm1, 1));
        tm1 = fmaxf(tm1, __shfl_xor_sync(0xffffffffu, tm1, 2));

        float nm0 = fmaxf(m0, tm0), nm1 = fmaxf(m1, tm1);
        float f0 = __expf(m0 - nm0), f1 = __expf(m1 - nm1);

        float rs0 = 0.f, rs1 = 0.f;
        #pragma unroll
        for (int nf = 0; nf < 8; nf++) {
            float p0 = __expf(S[nf][0] - nm0);
            float p1 = __expf(S[nf][1] - nm0);
            float p2 = __expf(S[nf][2] - nm1);
            float p3 = __expf(S[nf][3] - nm1);
            rs0 += p0 + p1;
            rs1 += p2 + p3;
            int cb = nf * 8 + 2 * t4;
            *reinterpret_cast<float2*>(&Ps[(wr + g) * PS_W + cb])     = make_float2(p0, p1);
            *reinterpret_cast<float2*>(&Ps[(wr + g + 8) * PS_W + cb]) = make_float2(p2, p3);
        }
        rs0 += __shfl_xor_sync(0xffffffffu, rs0, 1);
        rs0 += __shfl_xor_sync(0xffffffffu, rs0, 2);
        rs1 += __shfl_xor_sync(0xffffffffu, rs1, 1);
        rs1 += __shfl_xor_sync(0xffffffffu, rs1, 2);

        l0 = l0 * f0 + rs0;
        l1 = l1 * f1 + rs1;
        m0 = nm0; m1 = nm1;

        #pragma unroll
        for (int nf = 0; nf < 8; nf++) {
            Oacc[nf][0] *= f0; Oacc[nf][1] *= f0;
            Oacc[nf][2] *= f1; Oacc[nf][3] *= f1;
        }

        __syncwarp();

        // O += P V
        #pragma unroll
        for (int kk = 0; kk < 8; kk++) {
            unsigned a4[4];
            a4[0] = fbits(Ps[(wr + g) * PS_W + kk * 8 + t4]);
            a4[1] = fbits(Ps[(wr + g + 8) * PS_W + kk * 8 + t4]);
            a4[2] = fbits(Ps[(wr + g) * PS_W + kk * 8 + t4 + 4]);
            a4[3] = fbits(Ps[(wr + g + 8) * PS_W + kk * 8 + t4 + 4]);
            #pragma unroll
            for (int nf = 0; nf < 8; nf++) {
                unsigned b2[2];
                b2[0] = fbits(Vs[(kk * 8 + t4) * VS_W + nf * 8 + g]);
                b2[1] = fbits(Vs[(kk * 8 + t4 + 4) * VS_W + nf * 8 + g]);
                mma_tf32(Oacc[nf], a4, b2);
            }
        }

        __syncthreads();   // all warps done with stage s before it gets re-issued
    }

    // epilogue: normalize and write [B,T,C]
    float inv0 = 1.f / l0, inv1 = 1.f / l1;
    float* o0 = Out + ((long)b * T_ + q0 + wr + g) * C_ + h * HS_;
    float* o1 = Out + ((long)b * T_ + q0 + wr + g + 8) * C_ + h * HS_;
    #pragma unroll
    for (int nf = 0; nf < 8; nf++) {
        int c = nf * 8 + 2 * t4;
        float2 v0 = {Oacc[nf][0] * inv0, Oacc[nf][1] * inv0};
        float2 v1 = {Oacc[nf][2] * inv1, Oacc[nf][3] * inv1};
        *reinterpret_cast<float2*>(o0 + c) = v0;
        *reinterpret_cast<float2*>(o1 + c) = v1;
    }
}

// ---------------- orchestration ----------------
extern "C" void kernel_launch(void* const* d_in, const int* in_sizes, int n_in,
                              void* d_out, int out_size)
{
    const float* hidden = (const float*)d_in[0];
    const float* target = (const float*)d_in[1];
    const float* Wq_s = (const float*)d_in[2];
    const float* Wk_s = (const float*)d_in[3];
    const float* Wv_s = (const float*)d_in[4];
    const float* Wo_s = (const float*)d_in[5];
    const float* bo_s = (const float*)d_in[6];
    const float* Wq_x = (const float*)d_in[7];
    const float* Wk_x = (const float*)d_in[8];
    const float* Wv_x = (const float*)d_in[9];
    const float* Wo_x = (const float*)d_in[10];
    const float* bo_x = (const float*)d_in[11];
    const float* W1 = (const float*)d_in[12];
    const float* b1 = (const float*)d_in[13];
    const float* W2 = (const float*)d_in[14];
    const float* b2 = (const float*)d_in[15];
    const float* g1 = (const float*)d_in[16];
    const float* g2 = (const float*)d_in[17];
    const float* g3 = (const float*)d_in[18];
    const float* g4 = (const float*)d_in[19];

    float* t = (float*)d_out;

    float *xnorm, *hnorm, *q, *k, *v, *attn, *ff;
    cudaGetSymbolAddress((void**)&xnorm, g_xnorm);
    cudaGetSymbolAddress((void**)&hnorm, g_hnorm);
    cudaGetSymbolAddress((void**)&q, g_q);
    cudaGetSymbolAddress((void**)&k, g_k);
    cudaGetSymbolAddress((void**)&v, g_v);
    cudaGetSymbolAddress((void**)&attn, g_attn);
    cudaGetSymbolAddress((void**)&ff, g_ff);

    cudaFuncSetAttribute(flash_k, cudaFuncAttributeMaxDynamicSharedMemorySize, FLASH_SMEM);

    copy_k<<<(BTC_ / 4 + 255) / 256, 256>>>((float4*)t, (const float4*)target, BTC_ / 4);

    const long HCHS = (long)H_ * C_ * HS_;   // per-layer weight stride
    const long CHS  = (long)C_ * HS_;        // per-head weight stride
    const long BHT  = (long)H_ * T_ * HS_;   // per-b stride of q/k/v

    dim3 gQKV(12, T_ / 128, NB);             // 3 projections x 4 col-blocks, z=b
    dim3 gO(C_ / 128, BT_ / 128, 1);
    dim3 gF1(FF_ / 128, BT_ / 128, 1);
    dim3 gF2(C_ / 128, BT_ / 128, 1);
    dim3 gFl(T_ / 128, BH_, 1);

    for (int l = 0; l < NL; l++) {
        // ======== masked self-attention ========
        rmsnorm_k<<<BT_, 256>>>(t, g1 + (long)l * C_, xnorm);

        gemm128<<<gQKV, 256>>>(C_,
            xnorm, C_, (long)T_ * C_,
            Wq_s + l * HCHS, Wk_s + l * HCHS, Wv_s + l * HCHS, 0, CHS, 1,
            nullptr,
            q, k, v, 0, BHT, (long)T_ * HS_, 1,
            0, 0, 4);

        flash_k<<<gFl, 256, FLASH_SMEM>>>(q, k, v, attn, 1);

        gemm128<<<gO, 256>>>(C_,
            attn, C_, 0,
            Wo_s + (long)l * C_ * C_, Wo_s + (long)l * C_ * C_, Wo_s + (long)l * C_ * C_,
            C_, 0, 0,
            bo_s + (long)l * C_,
            t, t, t, C_, 0, 0, 0,
            1, 0, C_ / 128);

        // ======== cross-attention ========
        rmsnorm_k<<<BT_, 256>>>(hidden, g2 + (long)l * C_, hnorm);
        rmsnorm_k<<<BT_, 256>>>(t, g3 + (long)l * C_, xnorm);

        // Q from xnorm
        gemm128<<<dim3(4, T_ / 128, NB), 256>>>(C_,
            xnorm, C_, (long)T_ * C_,
            Wq_x + l * HCHS, Wq_x + l * HCHS, Wq_x + l * HCHS, 0, CHS, 1,
            nullptr,
            q, q, q, 0, BHT, (long)T_ * HS_, 1,
            0, 0, 4);
        // K,V from hnorm (fused pair)
        gemm128<<<dim3(8, T_ / 128, NB), 256>>>(C_,
            hnorm, C_, (long)T_ * C_,
            Wk_x + l * HCHS, Wv_x + l * HCHS, Wv_x + l * HCHS, 0, CHS, 1,
            nullptr,
            k, v, v, 0, BHT, (long)T_ * HS_, 1,
            0, 0, 4);

        flash_k<<<gFl, 256, FLASH_SMEM>>>(q, k, v, attn, 0);

        gemm128<<<gO, 256>>>(C_,
            attn, C_, 0,
            Wo_x + (long)l * C_ * C_, Wo_x + (long)l * C_ * C_, Wo_x + (long)l * C_ * C_,
            C_, 0, 0,
            bo_x + (long)l * C_,
            t, t, t, C_, 0, 0, 0,
            1, 0, C_ / 128);

        // ======== GELU FFN ========
        rmsnorm_k<<<BT_, 256>>>(t, g4 + (long)l * C_, xnorm);

        gemm128<<<gF1, 256>>>(C_,
            xnorm, C_, 0,
            W1 + (long)l * C_ * FF_, W1 + (long)l * C_ * FF_, W1 + (long)l * C_ * FF_,
            FF_, 0, 0,
            b1 + (long)l * FF_,
            ff, ff, ff, FF_, 0, 0, 0,
            0, 1, FF_ / 128);

        gemm128<<<gF2, 256>>>(FF_,
            ff, FF_, 0,
            W2 + (long)l * FF_ * C_, W2 + (long)l * FF_ * C_, W2 + (long)l * FF_ * C_,
            C_, 0, 0,
            b2 + (long)l * C_,
            t, t, t, C_, 0, 0, 0,
            1, 0, C_ / 128);
    }
}